// round 10
// baseline (speedup 1.0000x reference)
#include <cuda_runtime.h>
#include <cuda_bf16.h>
#include <math.h>
#include <stdint.h>

// ---------------------------------------------------------------------------
// Problem constants
// ---------------------------------------------------------------------------
#define NW 1000
#define ND 100
#define NF 100
#define TIw 512
#define HDw 128

#define NBLK 148
#define NT 512
#define TOTALTHR (NBLK * NT)

// Output layout (concatenated f32)
#define OFF_LAM   0
#define OFF_ZMAT  100
#define OFF_BETA  1000100
#define OFF_GAMMA 1001100
#define OFF_ETA   1001200
#define OFF_ZEV   1001300
#define OFF_H     101001300

#define KMAX 160

// ---------------------------------------------------------------------------
// Device scratch
// ---------------------------------------------------------------------------
__device__ __align__(16) float g_T1[NW * NF];
__device__ __align__(16) float g_H1[NW * NF];
__device__ __align__(16) float g_T2[NW * NF];
__device__ __align__(16) float g_E1[NW * NF];
__device__ __align__(16) float g_heli[NW * NF];
__device__ float g_y[NW];
__device__ float g_wp[NF];
__device__ int   g_kci[ND];
__device__ float g_norminv;

#define CSR_CAP 96
__device__ int   g_ccnt[NW];
__device__ int   g_ccol[NW * CSR_CAP];
__device__ float g_cval[NW * CSR_CAP];

// grid barrier state (round-4 proven)
__device__ unsigned g_barcnt = 0;
__device__ volatile unsigned g_bargen = 0;

__device__ __forceinline__ void gridbar() {
    __syncthreads();
    if (threadIdx.x == 0) {
        __threadfence();
        unsigned g = g_bargen;
        if (atomicAdd(&g_barcnt, 1u) == NBLK - 1) {
            g_barcnt = 0;
            __threadfence();
            g_bargen = g + 1;
        } else {
            while (g_bargen == g) { __nanosleep(128); }
        }
    }
    __syncthreads();
}

__device__ __forceinline__ float warp_sum(float v) {
#pragma unroll
    for (int o = 16; o; o >>= 1) v += __shfl_xor_sync(0xffffffffu, v, o);
    return v;
}

__device__ __forceinline__ float load_scalar(const void* p) {
    int v = *(const int*)p;
    if (v >= 0 && v <= 1000000) return (float)v;
    return *(const float*)p;
}

// ---------------------------------------------------------------------------
// Streams + events (static init; NOT during capture).
// Chain gets its own non-blocking stream: legacy default stream synchronizes
// with all streams, which is what serialized the fork in rounds 2-9.
// ---------------------------------------------------------------------------
struct SideRes {
    cudaStream_t s_side, s_chain;
    cudaEvent_t fork, zdone, cdone;
    SideRes() {
        int lo = 0, hi = 0;
        cudaDeviceGetStreamPriorityRange(&lo, &hi);
        cudaStreamCreateWithPriority(&s_side, cudaStreamNonBlocking, lo);
        cudaStreamCreateWithFlags(&s_chain, cudaStreamNonBlocking);
        cudaEventCreateWithFlags(&fork, cudaEventDisableTiming);
        cudaEventCreateWithFlags(&zdone, cudaEventDisableTiming);
        cudaEventCreateWithFlags(&cdone, cudaEventDisableTiming);
    }
};
static SideRes g_side;

// ---------------------------------------------------------------------------
// zev_zero (side stream): zero Z_event OUTSIDE the per-doc [0,160)^2 block.
// ---------------------------------------------------------------------------
#define ZA4 (100u * 160u * 210u)
#define ZB4 (100u * 840u * 250u)
#define ZT4 (ZA4 + ZB4)

__global__ void __launch_bounds__(256)
zev_zero(float* __restrict__ zev) {
    float4 z = {0.f, 0.f, 0.f, 0.f};
    float4* p = (float4*)zev;
    unsigned g = blockIdx.x * blockDim.x + threadIdx.x;
    unsigned stride = gridDim.x * blockDim.x;
    for (; g < ZT4; g += stride) {
        unsigned off4;
        if (g < ZA4) {
            unsigned d = g / 33600u;
            unsigned rem = g - d * 33600u;
            unsigned i = rem / 210u;
            unsigned q = rem - i * 210u;
            off4 = d * 250000u + i * 250u + 40u + q;
        } else {
            unsigned h = g - ZA4;
            unsigned d = h / 210000u;
            unsigned rem = h - d * 210000u;
            unsigned i2 = rem / 250u;
            unsigned q = rem - i2 * 250u;
            off4 = d * 250000u + (160u + i2) * 250u + q;
        }
        p[off4] = z;
    }
}

// ---------------------------------------------------------------------------
// Stage helpers for the fused persistent chain
// ---------------------------------------------------------------------------

// Dense C = op(A @ B + bias): B (+bias) cached in dynamic smem per block,
// thread-per-output grid-stride (A row loads are warp-broadcast).
__device__ __forceinline__ void dense_s(const float* __restrict__ A,
                                        const float* __restrict__ B,
                                        const float* __restrict__ bias,
                                        float* __restrict__ C, bool do_relu,
                                        float* sm, int t, int gtid) {
    for (int i = t; i < NF * NF / 4; i += NT)
        ((float4*)sm)[i] = ((const float4*)B)[i];
    if (t < NF) sm[NF * NF + t] = bias ? bias[t] : 0.f;
    __syncthreads();
    for (int idx = gtid; idx < NW * NF; idx += TOTALTHR) {
        int r = idx / NF, c = idx - r * NF;
        const float* Ar = A + (size_t)r * NF;
        float acc = sm[NF * NF + c];
#pragma unroll 4
        for (int k = 0; k < NF; ++k) acc = fmaf(Ar[k], sm[k * NF + c], acc);
        if (do_relu) acc = fmaxf(acc, 0.f);
        C[idx] = acc;
    }
}

// SpMM via CSR with shfl-broadcast of cols/vals (no serial LDG chains).
__device__ __forceinline__ void spmm_s(const float* __restrict__ X,
                                       float* __restrict__ C, bool do_relu,
                                       int wg, int lane) {
    if (wg >= NW) return;
    int nnz = g_ccnt[wg];
    const int* cols = g_ccol + wg * CSR_CAP;
    const float* vals = g_cval + wg * CSR_CAP;
    int   c0 = (lane < nnz) ? cols[lane] : 0;
    float v0 = (lane < nnz) ? vals[lane] : 0.f;
    int   c1 = (lane + 32 < nnz) ? cols[lane + 32] : 0;
    float v1 = (lane + 32 < nnz) ? vals[lane + 32] : 0.f;
    int   c2 = (lane + 64 < nnz) ? cols[lane + 64] : 0;
    float v2 = (lane + 64 < nnz) ? vals[lane + 64] : 0.f;

    float a0 = 0.f, a1 = 0.f, a2 = 0.f, a3 = 0.f;
    int lim0 = min(32, nnz);
    for (int s = 0; s < lim0; ++s) {
        int cc = __shfl_sync(0xffffffffu, c0, s);
        float vv = __shfl_sync(0xffffffffu, v0, s);
        const float* Xr = X + (size_t)cc * NF;
        a0 = fmaf(vv, Xr[lane], a0);
        a1 = fmaf(vv, Xr[lane + 32], a1);
        a2 = fmaf(vv, Xr[lane + 64], a2);
        if (lane < 4) a3 = fmaf(vv, Xr[lane + 96], a3);
    }
    if (nnz > 32) {
        int lim1 = min(32, nnz - 32);
        for (int s = 0; s < lim1; ++s) {
            int cc = __shfl_sync(0xffffffffu, c1, s);
            float vv = __shfl_sync(0xffffffffu, v1, s);
            const float* Xr = X + (size_t)cc * NF;
            a0 = fmaf(vv, Xr[lane], a0);
            a1 = fmaf(vv, Xr[lane + 32], a1);
            a2 = fmaf(vv, Xr[lane + 64], a2);
            if (lane < 4) a3 = fmaf(vv, Xr[lane + 96], a3);
        }
    }
    if (nnz > 64) {
        int lim2 = min(32, nnz - 64);
        for (int s = 0; s < lim2; ++s) {
            int cc = __shfl_sync(0xffffffffu, c2, s);
            float vv = __shfl_sync(0xffffffffu, v2, s);
            const float* Xr = X + (size_t)cc * NF;
            a0 = fmaf(vv, Xr[lane], a0);
            a1 = fmaf(vv, Xr[lane + 32], a1);
            a2 = fmaf(vv, Xr[lane + 64], a2);
            if (lane < 4) a3 = fmaf(vv, Xr[lane + 96], a3);
        }
    }
    if (do_relu) {
        a0 = fmaxf(a0, 0.f); a1 = fmaxf(a1, 0.f);
        a2 = fmaxf(a2, 0.f); a3 = fmaxf(a3, 0.f);
    }
    float* Cr = C + (size_t)wg * NF;
    Cr[lane] = a0; Cr[lane + 32] = a1; Cr[lane + 64] = a2;
    if (lane < 4) Cr[lane + 96] = a3;
}

#define PITCH_A 132
#define PITCH_B 68
#define FUSED_SMEM ((100 * PITCH_A + 100 * PITCH_B) * 4)   // 80000 bytes

// ---------------------------------------------------------------------------
// ONE persistent kernel for the whole chain (round-4 proven structure,
// upgraded stage implementations). No Z_event writes here.
// ---------------------------------------------------------------------------
__global__ void __launch_bounds__(NT)
fused_chain(const void* epoch, const void* epochs,
            const float* __restrict__ adj, const float* __restrict__ masks,
            const float* __restrict__ bows, const float* __restrict__ img,
            const float* __restrict__ W_g1, const float* __restrict__ W_g2,
            const float* __restrict__ W_h1, const float* __restrict__ b_h1,
            const float* __restrict__ W_h2, const float* __restrict__ b_h2,
            const float* __restrict__ W_mu2, const float* __restrict__ b_mu2,
            const float* __restrict__ W_eta2, const float* __restrict__ b_eta2,
            const float* __restrict__ W_gm2, const float* __restrict__ b_gm2,
            const float* __restrict__ w_m, const float* __restrict__ W_beta,
            const float* __restrict__ W_m1, const float* __restrict__ b_m1,
            const float* __restrict__ W_m2, const float* __restrict__ b_m2,
            float* __restrict__ oLam, float* __restrict__ oZ,
            float* __restrict__ oBeta, float* __restrict__ oGamma,
            float* __restrict__ oEta, float* __restrict__ oH) {
    extern __shared__ float sm[];
    __shared__ float sres[8];
    __shared__ int s_cnt_doc;

    const int t = threadIdx.x;
    const int lane = t & 31;
    const int wid = t >> 5;
    const int wg = blockIdx.x * (NT / 32) + wid;
    const int gtid = blockIdx.x * NT + t;

    // ---- S0: adj CSR gather (warp/row) + prune mask (last block) -----------
    if (wg < NW) {
        const float* row = adj + (size_t)wg * NW;
        int cnt = 0;
        for (int base = 0; base < NW; base += 32) {
            int c = base + lane;
            float v = (c < NW) ? row[c] : 0.f;
            unsigned m = __ballot_sync(0xffffffffu, v != 0.f);
            while (m) {
                int b = __ffs(m) - 1;
                m &= m - 1;
                float vb = __shfl_sync(0xffffffffu, v, b);
                if (lane == 0 && cnt < CSR_CAP) {
                    g_ccol[wg * CSR_CAP + cnt] = base + b;
                    g_cval[wg * CSR_CAP + cnt] = vb;
                }
                ++cnt;
            }
        }
        if (lane == 0) g_ccnt[wg] = min(cnt, CSR_CAP);
    }
    if (blockIdx.x == NBLK - 1 && t < NF) {
        float e1 = load_scalar(epoch), e2 = load_scalar(epochs);
        int j = (int)rintf((e1 / e2) * 0.3f * (float)NF);
        float wi = w_m[t];
        int rank = 0;
        for (int l = 0; l < NF; ++l) {
            float wl = w_m[l];
            if (wl < wi || (wl == wi && l < t)) ++rank;
        }
        g_wp[t] = (rank >= j) ? W_beta[t] : 0.f;
    }
    gridbar();

    // ---- S1: T1 = bows @ W_g1 ----------------------------------------------
    dense_s(bows, W_g1, nullptr, g_T1, false, sm, t, gtid);
    gridbar();

    // ---- S2: H1 = relu(adj @ T1) -------------------------------------------
    spmm_s(g_T1, g_H1, true, wg, lane);
    gridbar();

    // ---- S3: T2 = H1 @ W_g2 --------------------------------------------------
    dense_s(g_H1, W_g2, nullptr, g_T2, false, sm, t, gtid);
    gridbar();

    // ---- S4: H = adj @ T2 -> output ------------------------------------------
    spmm_s(g_T2, oH, false, wg, lane);
    gridbar();

    // ---- S5: E1 = relu(H@W_h1+b) ; y = H @ wp --------------------------------
    dense_s(oH, W_h1, b_h1, g_E1, true, sm, t, gtid);
    if (wg < NW) {
        const float* Hr = oH + (size_t)wg * NF;
        float p = Hr[lane] * g_wp[lane]
                + Hr[lane + 32] * g_wp[lane + 32]
                + Hr[lane + 64] * g_wp[lane + 64];
        if (lane < 4) p = fmaf(Hr[lane + 96], g_wp[lane + 96], p);
        p = warp_sum(p);
        if (lane == 0) g_y[wg] = p;
    }
    gridbar();

    // ---- S6: heli = l2norm(relu(E1@W_h2+b)) ; ||y|| (round-4 verbatim) ------
    {
        for (int i = t; i < NF * NF; i += NT) sm[i] = W_h2[i];
        if (t < NF) sm[NF * NF + t] = b_h2[t];
        __syncthreads();
        if (wg < NW) {
            const float* Ar = g_E1 + (size_t)wg * NF;
            float a0 = sm[NF * NF + lane];
            float a1 = sm[NF * NF + lane + 32];
            float a2 = sm[NF * NF + lane + 64];
            float a3 = (lane < 4) ? sm[NF * NF + lane + 96] : 0.f;
            for (int k = 0; k < NF; ++k) {
                float e = Ar[k];
                const float* Wk = sm + k * NF;
                a0 = fmaf(e, Wk[lane], a0);
                a1 = fmaf(e, Wk[lane + 32], a1);
                a2 = fmaf(e, Wk[lane + 64], a2);
                if (lane < 4) a3 = fmaf(e, Wk[lane + 96], a3);
            }
            a0 = fmaxf(a0, 0.f); a1 = fmaxf(a1, 0.f);
            a2 = fmaxf(a2, 0.f); a3 = fmaxf(a3, 0.f);
            float ss = a0 * a0 + a1 * a1 + a2 * a2 + a3 * a3;
            ss = warp_sum(ss);
            float inv = 1.f / fmaxf(sqrtf(ss), 1e-12f);
            float* Cr = g_heli + (size_t)wg * NF;
            Cr[lane] = a0 * inv; Cr[lane + 32] = a1 * inv; Cr[lane + 64] = a2 * inv;
            if (lane < 4) Cr[lane + 96] = a3 * inv;
        }
        if (blockIdx.x == 0) {
            __syncthreads();
            float v = 0.f;
            for (int r = t; r < NW; r += NT) v = fmaf(g_y[r], g_y[r], v);
            sm[t] = v;
            __syncthreads();
            for (int s = 256; s; s >>= 1) {
                if (t < s) sm[t] += sm[t + s];
                __syncthreads();
            }
            if (t == 0) g_norminv = 1.f / fmaxf(sqrtf(sm[0]), 1e-12f);
        }
    }
    gridbar();

    // ---- S7: Z_ tiles (blocks <128, round-4 verbatim) ; beta_ write ---------
    if (blockIdx.x == NBLK - 1) {
        float ninv = g_norminv;
        for (int r = t; r < NW; r += NT) oBeta[r] = g_y[r] * ninv;
    }
    if (blockIdx.x < 128) {
        float* sA = sm;
        float* sB = sm + 100 * PITCH_A;
        int rowTile = blockIdx.x >> 4;
        int colTile = blockIdx.x & 15;
        int rb = rowTile * 128, jb = colTile * 64;
        for (int i = t; i < 128 * NF; i += NT) {
            int rr = i / NF, kk = i - (i / NF) * NF;
            int gr = rb + rr;
            sA[kk * PITCH_A + rr] = (gr < NW) ? g_heli[(size_t)gr * NF + kk] : 0.f;
        }
        for (int i = t; i < 64 * NF; i += NT) {
            int rr = i / NF, kk = i - (i / NF) * NF;
            int gc = jb + rr;
            sB[kk * PITCH_B + rr] = (gc < NW) ? g_heli[(size_t)gc * NF + kk] : 0.f;
        }
        __syncthreads();
        int tx = t & 15, ty = t >> 4;
        float acc[4][4] = {};
        for (int kk = 0; kk < NF; ++kk) {
            float4 a = *(const float4*)&sA[kk * PITCH_A + ty * 4];
            float4 b = *(const float4*)&sB[kk * PITCH_B + tx * 4];
            float av[4] = {a.x, a.y, a.z, a.w};
            float bv[4] = {b.x, b.y, b.z, b.w};
#pragma unroll
            for (int r = 0; r < 4; ++r)
#pragma unroll
                for (int c = 0; c < 4; ++c)
                    acc[r][c] = fmaf(av[r], bv[c], acc[r][c]);
        }
#pragma unroll
        for (int r = 0; r < 4; ++r) {
            int gr = rb + ty * 4 + r;
            if (gr >= NW) continue;
#pragma unroll
            for (int c = 0; c < 4; ++c) {
                int gc = jb + tx * 4 + c;
                if (gc >= NW) continue;
                oZ[(size_t)gr * NW + gc] = fmaxf(acc[r][c], 0.f);
            }
        }
    }
    gridbar();

    // ---- S8: per-doc epilogue (blocks 0..99, round-4 verbatim + 4-acc MLP) --
    if (blockIdx.x < ND) {
        int d = blockIdx.x;
        int* cols = (int*)sm;          // [160]
        float* red = sm + 160;         // [512]
        float* hp = red + NT;          // [128]
        float* simg = hp + 128;        // [512]

        if (wid == 0) {
            const float* mrow = masks + (size_t)d * NW;
            int cnt = 0;
            for (int base = 0; base < NW; base += 32) {
                int c = base + lane;
                float v = (c < NW) ? mrow[c] : 0.f;
                unsigned m = __ballot_sync(0xffffffffu, v != 0.f);
                while (m) {
                    int b = __ffs(m) - 1;
                    m &= m - 1;
                    if (lane == 0 && cnt < KMAX) cols[cnt] = base + b;
                    ++cnt;
                }
            }
            if (lane == 0) s_cnt_doc = min(cnt, KMAX);
        }
        __syncthreads();
        int cnt = s_cnt_doc;
        float fk = (float)cnt;

        float sv = 0.f;
        if (t < NF) {
            float hpv = 0.f;
#pragma unroll 4
            for (int q = 0; q < cnt; ++q) {
                int c = cols[q];
                hpv += oH[(size_t)c * NF + t];
                sv += g_heli[(size_t)c * NF + t];
            }
            hp[t] = hpv / fmaxf(fk, 1.f);
        }
        red[t] = (t < NF) ? sv * sv : 0.f;
        __syncthreads();
        for (int s = 256; s; s >>= 1) { if (t < s) red[t] += red[t + s]; __syncthreads(); }
        if (t == 0) sres[0] = red[0];
        __syncthreads();

        red[t] = (t < cnt) ? oBeta[cols[t]] : 0.f;
        __syncthreads();
        for (int s = 256; s; s >>= 1) { if (t < s) red[t] += red[t + s]; __syncthreads(); }
        if (t == 0) sres[1] = red[0];
        __syncthreads();

        float hpt = (t < NF) ? hp[t] : 0.f;
        red[t] = (t < NF) ? hpt * W_mu2[t] : 0.f;
        __syncthreads();
        for (int s = 256; s; s >>= 1) { if (t < s) red[t] += red[t + s]; __syncthreads(); }
        if (t == 0) sres[2] = fmaxf(red[0] + b_mu2[0], 0.f);
        __syncthreads();
        red[t] = (t < NF) ? hpt * W_eta2[t] : 0.f;
        __syncthreads();
        for (int s = 256; s; s >>= 1) { if (t < s) red[t] += red[t + s]; __syncthreads(); }
        if (t == 0) sres[3] = fmaxf(red[0] + b_eta2[0], 0.f);
        __syncthreads();
        red[t] = (t < NF) ? hpt * W_gm2[t] : 0.f;
        __syncthreads();
        for (int s = 256; s; s >>= 1) { if (t < s) red[t] += red[t + s]; __syncthreads(); }
        if (t == 0) sres[4] = fmaxf(red[0] + b_gm2[0], 0.f);
        __syncthreads();

        for (int k = t; k < TIw; k += NT) simg[k] = img[(size_t)d * TIw + k];
        __syncthreads();
        float contrib = 0.f;
        if (t < HDw) {
            float h0 = b_m1[t], h1 = 0.f, h2 = 0.f, h3 = 0.f;
#pragma unroll 4
            for (int k = 0; k < TIw; k += 4) {
                h0 = fmaf(simg[k],     W_m1[(size_t)k * HDw + t],       h0);
                h1 = fmaf(simg[k + 1], W_m1[(size_t)(k + 1) * HDw + t], h1);
                h2 = fmaf(simg[k + 2], W_m1[(size_t)(k + 2) * HDw + t], h2);
                h3 = fmaf(simg[k + 3], W_m1[(size_t)(k + 3) * HDw + t], h3);
            }
            contrib = fmaxf((h0 + h1) + (h2 + h3), 0.f) * W_m2[t];
        }
        red[t] = contrib;
        __syncthreads();
        for (int s = 256; s; s >>= 1) { if (t < s) red[t] += red[t + s]; __syncthreads(); }

        if (t == 0) {
            float li = red[0] + b_m2[0];
            float Z = fmaxf(0.5f * (sres[0] - fk), 0.f);
            float inner = sres[2] + sres[1] + sres[3] * expf(-sres[4] * Z);
            float lt = 1.f / (1.f + expf(-inner));
            oLam[d] = 1.f / (1.f + expf(-(lt + li)));
            oEta[d] = sres[3];
            oGamma[d] = sres[4];
            g_kci[d] = cnt;
        }
    }
}

// ---------------------------------------------------------------------------
// Z_event patch: per-doc top-left [0,160)^2 block (computed or zero).
// ---------------------------------------------------------------------------
__global__ void __launch_bounds__(256)
zev_patch(const float* __restrict__ oZ, float* __restrict__ zev) {
    unsigned g = blockIdx.x * 256u + threadIdx.x;   // < 640000
    if (g >= 640000u) return;
    unsigned d = g / 6400u;
    unsigned rem = g - d * 6400u;
    unsigned i = rem / 40u;
    unsigned q = rem - i * 40u;
    unsigned j0 = q << 2;
    int kd = g_kci[d];
    float4 v = {0.f, 0.f, 0.f, 0.f};
    if ((int)i < kd) {
        const float* zr = oZ + (size_t)i * NW + j0;
        float* vv = (float*)&v;
#pragma unroll
        for (int c = 0; c < 4; ++c) {
            int j = (int)j0 + c;
            if (j < kd && j != (int)i) {
                float tt = 2.f - 2.f * zr[c];
                vv[c] = expf(-tt * tt);
            }
        }
    }
    *(float4*)(zev + (size_t)d * NW * NW + (size_t)i * NW + j0) = v;
}

// ---------------------------------------------------------------------------
// Host launch: 3 nodes — zev_zero (side stream) || fused_chain (chain stream),
// then zev_patch (legacy) after both.
// ---------------------------------------------------------------------------
extern "C" void kernel_launch(void* const* d_in, const int* in_sizes, int n_in,
                              void* d_out, int out_size) {
    (void)in_sizes; (void)n_in; (void)out_size;
    const void*  epoch  = d_in[0];
    const void*  epochs = d_in[1];
    const float* adj    = (const float*)d_in[2];
    const float* masks  = (const float*)d_in[3];
    const float* bows   = (const float*)d_in[4];
    const float* img    = (const float*)d_in[5];
    const float* W_g1   = (const float*)d_in[6];
    const float* W_g2   = (const float*)d_in[7];
    const float* W_h1   = (const float*)d_in[8];
    const float* b_h1   = (const float*)d_in[9];
    const float* W_h2   = (const float*)d_in[10];
    const float* b_h2   = (const float*)d_in[11];
    const float* W_mu2  = (const float*)d_in[12];
    const float* b_mu2  = (const float*)d_in[13];
    const float* W_eta2 = (const float*)d_in[14];
    const float* b_eta2 = (const float*)d_in[15];
    const float* W_gm2  = (const float*)d_in[16];
    const float* b_gm2  = (const float*)d_in[17];
    const float* w_m    = (const float*)d_in[18];
    const float* W_beta = (const float*)d_in[19];
    const float* W_m1   = (const float*)d_in[20];
    const float* b_m1   = (const float*)d_in[21];
    const float* W_m2   = (const float*)d_in[22];
    const float* b_m2   = (const float*)d_in[23];

    float* out = (float*)d_out;
    float* oLam   = out + OFF_LAM;
    float* oZ     = out + OFF_ZMAT;
    float* oBeta  = out + OFF_BETA;
    float* oGamma = out + OFF_GAMMA;
    float* oEta   = out + OFF_ETA;
    float* oZev   = out + OFF_ZEV;
    float* oH     = out + OFF_H;

    // One-time attribute opt-in (outside capture on the first/correctness call;
    // skipped during graph capture — same pattern as the passing round 4).
    static bool attr_set = false;
    if (!attr_set) {
        cudaFuncSetAttribute(fused_chain, cudaFuncAttributeMaxDynamicSharedMemorySize,
                             FUSED_SMEM);
        attr_set = true;
    }

    // fork
    cudaEventRecord(g_side.fork, 0);

    // side stream: Z_event zero region
    cudaStreamWaitEvent(g_side.s_side, g_side.fork, 0);
    zev_zero<<<296, 256, 0, g_side.s_side>>>(oZev);
    cudaEventRecord(g_side.zdone, g_side.s_side);

    // chain stream: single persistent kernel for the whole chain
    cudaStreamWaitEvent(g_side.s_chain, g_side.fork, 0);
    fused_chain<<<NBLK, NT, FUSED_SMEM, g_side.s_chain>>>(
        epoch, epochs, adj, masks, bows, img,
        W_g1, W_g2, W_h1, b_h1, W_h2, b_h2,
        W_mu2, b_mu2, W_eta2, b_eta2, W_gm2, b_gm2,
        w_m, W_beta, W_m1, b_m1, W_m2, b_m2,
        oLam, oZ, oBeta, oGamma, oEta, oH);
    cudaEventRecord(g_side.cdone, g_side.s_chain);

    // join on legacy stream, then patch
    cudaStreamWaitEvent(0, g_side.zdone, 0);
    cudaStreamWaitEvent(0, g_side.cdone, 0);
    zev_patch<<<2500, 256>>>(oZ, oZev);
}

// round 11
// speedup vs baseline: 1.0062x; 1.0062x over previous
#include <cuda_runtime.h>
#include <cuda_bf16.h>
#include <math.h>
#include <stdint.h>

// ---------------------------------------------------------------------------
// Problem constants
// ---------------------------------------------------------------------------
#define NW 1000
#define ND 100
#define NF 100
#define TIw 512
#define HDw 128

#define NBLK 148
#define NT 512
#define NCW 8                 // compute warps per block (warps 0..7)
#define NCT 256               // compute threads per block
#define TOTC (NBLK * NCT)     // 37888 compute threads
#define TOTCW (NBLK * NCW)    // 1184 compute warps

// Output layout (concatenated f32)
#define OFF_LAM   0
#define OFF_ZMAT  100
#define OFF_BETA  1000100
#define OFF_GAMMA 1001100
#define OFF_ETA   1001200
#define OFF_ZEV   1001300
#define OFF_H     101001300

#define KMAX 160

// ---------------------------------------------------------------------------
// Device scratch
// ---------------------------------------------------------------------------
__device__ __align__(16) float g_T1[NW * NF];
__device__ __align__(16) float g_H1[NW * NF];
__device__ __align__(16) float g_T2[NW * NF];
__device__ __align__(16) float g_E1[NW * NF];
__device__ __align__(16) float g_heli[NW * NF];
__device__ float g_y[NW];
__device__ float g_wp[NF];
__device__ int   g_kci[ND];
__device__ float g_norminv;

#define CSR_CAP 96
__device__ int   g_ccnt[NW];
__device__ int   g_ccol[NW * CSR_CAP];
__device__ float g_cval[NW * CSR_CAP];

// compute-warps-only grid barrier state
__device__ unsigned g_barcnt = 0;
__device__ volatile unsigned g_bargen = 0;

// bar.sync 1, 256: intra-block barrier over compute warps ONLY (writers never
// participate). Same release/arrive protocol that passed correctness in r4/r10.
#define CBAR_LOCAL() asm volatile("bar.sync 1, 256;" ::: "memory")

__device__ __forceinline__ void cbar() {
    CBAR_LOCAL();
    if (threadIdx.x == 0) {
        __threadfence();
        unsigned g = g_bargen;
        if (atomicAdd(&g_barcnt, 1u) == NBLK - 1) {
            g_barcnt = 0;
            __threadfence();
            g_bargen = g + 1;
        } else {
            while (g_bargen == g) { __nanosleep(64); }
        }
    }
    CBAR_LOCAL();
}

__device__ __forceinline__ float warp_sum(float v) {
#pragma unroll
    for (int o = 16; o; o >>= 1) v += __shfl_xor_sync(0xffffffffu, v, o);
    return v;
}

__device__ __forceinline__ float load_scalar(const void* p) {
    int v = *(const int*)p;
    if (v >= 0 && v <= 1000000) return (float)v;
    return *(const float*)p;
}

// ---------------------------------------------------------------------------
// Stage helpers (compute warps, 256 threads/block)
// ---------------------------------------------------------------------------

// Dense C = op(A @ B + bias): B (+bias) cached in smem, thread-per-output.
__device__ __forceinline__ void dense_s(const float* __restrict__ A,
                                        const float* __restrict__ B,
                                        const float* __restrict__ bias,
                                        float* __restrict__ C, bool do_relu,
                                        float* sm, int t, int ct) {
    for (int i = t; i < NF * NF / 4; i += NCT)
        ((float4*)sm)[i] = ((const float4*)B)[i];
    if (t < NF) sm[NF * NF + t] = bias ? bias[t] : 0.f;
    CBAR_LOCAL();
    for (int idx = ct; idx < NW * NF; idx += TOTC) {
        int r = idx / NF, c = idx - r * NF;
        const float* Ar = A + (size_t)r * NF;
        float acc = sm[NF * NF + c];
#pragma unroll 4
        for (int k = 0; k < NF; ++k) acc = fmaf(Ar[k], sm[k * NF + c], acc);
        if (do_relu) acc = fmaxf(acc, 0.f);
        C[idx] = acc;
    }
}

// SpMM one row via CSR with shfl-broadcast (correctness-proven in round 10).
__device__ __forceinline__ void spmm_row(const float* __restrict__ X,
                                         float* __restrict__ C, bool do_relu,
                                         int row, int lane) {
    int nnz = g_ccnt[row];
    const int* cols = g_ccol + row * CSR_CAP;
    const float* vals = g_cval + row * CSR_CAP;
    int   c0 = (lane < nnz) ? cols[lane] : 0;
    float v0 = (lane < nnz) ? vals[lane] : 0.f;
    int   c1 = (lane + 32 < nnz) ? cols[lane + 32] : 0;
    float v1 = (lane + 32 < nnz) ? vals[lane + 32] : 0.f;
    int   c2 = (lane + 64 < nnz) ? cols[lane + 64] : 0;
    float v2 = (lane + 64 < nnz) ? vals[lane + 64] : 0.f;

    float a0 = 0.f, a1 = 0.f, a2 = 0.f, a3 = 0.f;
    int lim0 = min(32, nnz);
    for (int s = 0; s < lim0; ++s) {
        int cc = __shfl_sync(0xffffffffu, c0, s);
        float vv = __shfl_sync(0xffffffffu, v0, s);
        const float* Xr = X + (size_t)cc * NF;
        a0 = fmaf(vv, Xr[lane], a0);
        a1 = fmaf(vv, Xr[lane + 32], a1);
        a2 = fmaf(vv, Xr[lane + 64], a2);
        if (lane < 4) a3 = fmaf(vv, Xr[lane + 96], a3);
    }
    if (nnz > 32) {
        int lim1 = min(32, nnz - 32);
        for (int s = 0; s < lim1; ++s) {
            int cc = __shfl_sync(0xffffffffu, c1, s);
            float vv = __shfl_sync(0xffffffffu, v1, s);
            const float* Xr = X + (size_t)cc * NF;
            a0 = fmaf(vv, Xr[lane], a0);
            a1 = fmaf(vv, Xr[lane + 32], a1);
            a2 = fmaf(vv, Xr[lane + 64], a2);
            if (lane < 4) a3 = fmaf(vv, Xr[lane + 96], a3);
        }
    }
    if (nnz > 64) {
        int lim2 = min(32, nnz - 64);
        for (int s = 0; s < lim2; ++s) {
            int cc = __shfl_sync(0xffffffffu, c2, s);
            float vv = __shfl_sync(0xffffffffu, v2, s);
            const float* Xr = X + (size_t)cc * NF;
            a0 = fmaf(vv, Xr[lane], a0);
            a1 = fmaf(vv, Xr[lane + 32], a1);
            a2 = fmaf(vv, Xr[lane + 64], a2);
            if (lane < 4) a3 = fmaf(vv, Xr[lane + 96], a3);
        }
    }
    if (do_relu) {
        a0 = fmaxf(a0, 0.f); a1 = fmaxf(a1, 0.f);
        a2 = fmaxf(a2, 0.f); a3 = fmaxf(a3, 0.f);
    }
    float* Cr = C + (size_t)row * NF;
    Cr[lane] = a0; Cr[lane + 32] = a1; Cr[lane + 64] = a2;
    if (lane < 4) Cr[lane + 96] = a3;
}

// smem plan (floats):
//   dense/S6 : [0..9999] W, [10000..10099] bias, [10200..10455] reduce
//   S7 tiles : sA [0..6799] (pitch 68), sB [6800..13599]
//   S8 doc   : cols(int)[0..159], red[160..415], hp[416..543], simg[544..1055]
#define PITCH7 68
#define FUSED_SMEM (13700 * 4)

// ---------------------------------------------------------------------------
// ONE kernel: warps 0-7 chain+patch, warps 8-15 stream Z_event zeros.
// ---------------------------------------------------------------------------
__global__ void __launch_bounds__(NT)
fused_ws(const void* epoch, const void* epochs,
         const float* __restrict__ adj, const float* __restrict__ masks,
         const float* __restrict__ bows, const float* __restrict__ img,
         const float* __restrict__ W_g1, const float* __restrict__ W_g2,
         const float* __restrict__ W_h1, const float* __restrict__ b_h1,
         const float* __restrict__ W_h2, const float* __restrict__ b_h2,
         const float* __restrict__ W_mu2, const float* __restrict__ b_mu2,
         const float* __restrict__ W_eta2, const float* __restrict__ b_eta2,
         const float* __restrict__ W_gm2, const float* __restrict__ b_gm2,
         const float* __restrict__ w_m, const float* __restrict__ W_beta,
         const float* __restrict__ W_m1, const float* __restrict__ b_m1,
         const float* __restrict__ W_m2, const float* __restrict__ b_m2,
         float* __restrict__ oLam, float* __restrict__ oZ,
         float* __restrict__ oBeta, float* __restrict__ oGamma,
         float* __restrict__ oEta, float* __restrict__ oZev,
         float* __restrict__ oH) {
    extern __shared__ float sm[];
    __shared__ float sres[8];
    __shared__ int s_cnt_doc;

    const int t = threadIdx.x;
    const int lane = t & 31;
    const int wid = t >> 5;

    if (wid >= NCW) {
        // ================= WRITER WARPS: stream Z_event zero region =========
        // rows r = d*1000 + i ; i<160 -> float4 cols [40,250) ; else [0,250)
        float4 z4 = {0.f, 0.f, 0.f, 0.f};
        int ww = blockIdx.x * NCW + (wid - NCW);          // 0..1183
        for (int r = ww; r < ND * NW; r += TOTCW) {
            int d = r / NW;
            int i = r - d * NW;
            float4* dst = (float4*)(oZev + (size_t)d * NW * NW + (size_t)i * NW);
            int q0 = (i < KMAX) ? 40 : 0;
            for (int q = q0 + lane; q < 250; q += 32) dst[q] = z4;
        }
        return;
    }

    // ==================== COMPUTE WARPS: the chain =========================
    const int cw = blockIdx.x * NCW + wid;     // 0..1183
    const int ct = blockIdx.x * NCT + t;       // 0..37887

    // ---- S0: adj CSR gather (warp-per-row loop) + prune mask --------------
    for (int row = cw; row < NW; row += TOTCW) {
        const float* rp = adj + (size_t)row * NW;
        int cnt = 0;
        for (int base = 0; base < NW; base += 32) {
            int c = base + lane;
            float v = (c < NW) ? rp[c] : 0.f;
            unsigned m = __ballot_sync(0xffffffffu, v != 0.f);
            while (m) {
                int b = __ffs(m) - 1;
                m &= m - 1;
                float vb = __shfl_sync(0xffffffffu, v, b);
                if (lane == 0 && cnt < CSR_CAP) {
                    g_ccol[row * CSR_CAP + cnt] = base + b;
                    g_cval[row * CSR_CAP + cnt] = vb;
                }
                ++cnt;
            }
        }
        if (lane == 0) g_ccnt[row] = min(cnt, CSR_CAP);
    }
    if (blockIdx.x == NBLK - 1 && t < NF) {
        float e1 = load_scalar(epoch), e2 = load_scalar(epochs);
        int j = (int)rintf((e1 / e2) * 0.3f * (float)NF);
        float wi = w_m[t];
        int rank = 0;
        for (int l = 0; l < NF; ++l) {
            float wl = w_m[l];
            if (wl < wi || (wl == wi && l < t)) ++rank;
        }
        g_wp[t] = (rank >= j) ? W_beta[t] : 0.f;
    }
    cbar();

    // ---- S1: T1 = bows @ W_g1 ----------------------------------------------
    dense_s(bows, W_g1, nullptr, g_T1, false, sm, t, ct);
    cbar();

    // ---- S2: H1 = relu(adj @ T1) -------------------------------------------
    for (int row = cw; row < NW; row += TOTCW) spmm_row(g_T1, g_H1, true, row, lane);
    cbar();

    // ---- S3: T2 = H1 @ W_g2 -------------------------------------------------
    dense_s(g_H1, W_g2, nullptr, g_T2, false, sm, t, ct);
    cbar();

    // ---- S4: H = adj @ T2 -> output -----------------------------------------
    for (int row = cw; row < NW; row += TOTCW) spmm_row(g_T2, oH, false, row, lane);
    cbar();

    // ---- S5: E1 = relu(H@W_h1+b) ; y = H @ wp --------------------------------
    dense_s(oH, W_h1, b_h1, g_E1, true, sm, t, ct);
    for (int row = cw; row < NW; row += TOTCW) {
        const float* Hr = oH + (size_t)row * NF;
        float p = Hr[lane] * g_wp[lane]
                + Hr[lane + 32] * g_wp[lane + 32]
                + Hr[lane + 64] * g_wp[lane + 64];
        if (lane < 4) p = fmaf(Hr[lane + 96], g_wp[lane + 96], p);
        p = warp_sum(p);
        if (lane == 0) g_y[row] = p;
    }
    cbar();

    // ---- S6: heli = l2norm(relu(E1@W_h2+b)) ; ||y|| --------------------------
    {
        for (int i = t; i < NF * NF; i += NCT) sm[i] = W_h2[i];
        if (t < NF) sm[NF * NF + t] = b_h2[t];
        CBAR_LOCAL();
        for (int row = cw; row < NW; row += TOTCW) {
            const float* Ar = g_E1 + (size_t)row * NF;
            float a0 = sm[NF * NF + lane];
            float a1 = sm[NF * NF + lane + 32];
            float a2 = sm[NF * NF + lane + 64];
            float a3 = (lane < 4) ? sm[NF * NF + lane + 96] : 0.f;
            for (int k = 0; k < NF; ++k) {
                float e = Ar[k];
                const float* Wk = sm + k * NF;
                a0 = fmaf(e, Wk[lane], a0);
                a1 = fmaf(e, Wk[lane + 32], a1);
                a2 = fmaf(e, Wk[lane + 64], a2);
                if (lane < 4) a3 = fmaf(e, Wk[lane + 96], a3);
            }
            a0 = fmaxf(a0, 0.f); a1 = fmaxf(a1, 0.f);
            a2 = fmaxf(a2, 0.f); a3 = fmaxf(a3, 0.f);
            float ss = a0 * a0 + a1 * a1 + a2 * a2 + a3 * a3;
            ss = warp_sum(ss);
            float inv = 1.f / fmaxf(sqrtf(ss), 1e-12f);
            float* Cr = g_heli + (size_t)row * NF;
            Cr[lane] = a0 * inv; Cr[lane + 32] = a1 * inv; Cr[lane + 64] = a2 * inv;
            if (lane < 4) Cr[lane + 96] = a3 * inv;
        }
        if (blockIdx.x == 0) {
            CBAR_LOCAL();
            float v = 0.f;
            for (int r = t; r < NW; r += NCT) v = fmaf(g_y[r], g_y[r], v);
            float* red = sm + 10200;
            red[t] = v;
            CBAR_LOCAL();
            for (int s = 128; s; s >>= 1) {
                if (t < s) red[t] += red[t + s];
                CBAR_LOCAL();
            }
            if (t == 0) g_norminv = 1.f / fmaxf(sqrtf(red[0]), 1e-12f);
        }
    }
    cbar();

    // ---- S7: beta_ write ; Z_ = relu(heli@heli^T), 64x64 tiles, looped ------
    if (blockIdx.x == NBLK - 1) {
        float ninv = g_norminv;
        for (int r = t; r < NW; r += NCT) oBeta[r] = g_y[r] * ninv;
    }
    {
        float* sA = sm;
        float* sB = sm + 100 * PITCH7;
        for (int ti = blockIdx.x; ti < 256; ti += NBLK) {
            int rb = (ti >> 4) * 64, jb = (ti & 15) * 64;
            for (int i = t; i < 64 * NF; i += NCT) {
                int rr = i / NF, kk = i - (i / NF) * NF;
                int gr = rb + rr, gc = jb + rr;
                sA[kk * PITCH7 + rr] = (gr < NW) ? g_heli[(size_t)gr * NF + kk] : 0.f;
                sB[kk * PITCH7 + rr] = (gc < NW) ? g_heli[(size_t)gc * NF + kk] : 0.f;
            }
            CBAR_LOCAL();
            int tx = t & 15, ty = t >> 4;
            float acc[4][4] = {};
            for (int kk = 0; kk < NF; ++kk) {
                float4 a = *(const float4*)&sA[kk * PITCH7 + ty * 4];
                float4 b = *(const float4*)&sB[kk * PITCH7 + tx * 4];
                float av[4] = {a.x, a.y, a.z, a.w};
                float bv[4] = {b.x, b.y, b.z, b.w};
#pragma unroll
                for (int r = 0; r < 4; ++r)
#pragma unroll
                    for (int c = 0; c < 4; ++c)
                        acc[r][c] = fmaf(av[r], bv[c], acc[r][c]);
            }
#pragma unroll
            for (int r = 0; r < 4; ++r) {
                int gr = rb + ty * 4 + r;
                if (gr >= NW) continue;
#pragma unroll
                for (int c = 0; c < 4; ++c) {
                    int gc = jb + tx * 4 + c;
                    if (gc >= NW) continue;
                    oZ[(size_t)gr * NW + gc] = fmaxf(acc[r][c], 0.f);
                }
            }
            CBAR_LOCAL();
        }
    }
    cbar();

    // ---- S8: per-doc epilogue (blocks 0..99) ---------------------------------
    if (blockIdx.x < ND) {
        int d = blockIdx.x;
        int* cols = (int*)sm;             // [160]
        float* red = sm + 160;            // [256]
        float* hp = sm + 416;             // [128]
        float* simg = sm + 544;           // [512]

        if (wid == 0) {
            const float* mrow = masks + (size_t)d * NW;
            int cnt = 0;
            for (int base = 0; base < NW; base += 32) {
                int c = base + lane;
                float v = (c < NW) ? mrow[c] : 0.f;
                unsigned m = __ballot_sync(0xffffffffu, v != 0.f);
                while (m) {
                    int b = __ffs(m) - 1;
                    m &= m - 1;
                    if (lane == 0 && cnt < KMAX) cols[cnt] = base + b;
                    ++cnt;
                }
            }
            if (lane == 0) s_cnt_doc = min(cnt, KMAX);
        }
        CBAR_LOCAL();
        int cnt = s_cnt_doc;
        float fk = (float)cnt;

        float sv = 0.f;
        if (t < NF) {
            float hpv = 0.f;
#pragma unroll 4
            for (int q = 0; q < cnt; ++q) {
                int c = cols[q];
                hpv += oH[(size_t)c * NF + t];
                sv += g_heli[(size_t)c * NF + t];
            }
            hp[t] = hpv / fmaxf(fk, 1.f);
        }
        red[t] = (t < NF) ? sv * sv : 0.f;
        CBAR_LOCAL();
        for (int s = 128; s; s >>= 1) { if (t < s) red[t] += red[t + s]; CBAR_LOCAL(); }
        if (t == 0) sres[0] = red[0];
        CBAR_LOCAL();

        red[t] = (t < cnt) ? oBeta[cols[t]] : 0.f;
        CBAR_LOCAL();
        for (int s = 128; s; s >>= 1) { if (t < s) red[t] += red[t + s]; CBAR_LOCAL(); }
        if (t == 0) sres[1] = red[0];
        CBAR_LOCAL();

        float hpt = (t < NF) ? hp[t] : 0.f;
        red[t] = (t < NF) ? hpt * W_mu2[t] : 0.f;
        CBAR_LOCAL();
        for (int s = 128; s; s >>= 1) { if (t < s) red[t] += red[t + s]; CBAR_LOCAL(); }
        if (t == 0) sres[2] = fmaxf(red[0] + b_mu2[0], 0.f);
        CBAR_LOCAL();
        red[t] = (t < NF) ? hpt * W_eta2[t] : 0.f;
        CBAR_LOCAL();
        for (int s = 128; s; s >>= 1) { if (t < s) red[t] += red[t + s]; CBAR_LOCAL(); }
        if (t == 0) sres[3] = fmaxf(red[0] + b_eta2[0], 0.f);
        CBAR_LOCAL();
        red[t] = (t < NF) ? hpt * W_gm2[t] : 0.f;
        CBAR_LOCAL();
        for (int s = 128; s; s >>= 1) { if (t < s) red[t] += red[t + s]; CBAR_LOCAL(); }
        if (t == 0) sres[4] = fmaxf(red[0] + b_gm2[0], 0.f);
        CBAR_LOCAL();

        for (int k = t; k < TIw; k += NCT) simg[k] = img[(size_t)d * TIw + k];
        CBAR_LOCAL();
        float contrib = 0.f;
        if (t < HDw) {
            float h0 = b_m1[t], h1 = 0.f, h2 = 0.f, h3 = 0.f;
#pragma unroll 4
            for (int k = 0; k < TIw; k += 4) {
                h0 = fmaf(simg[k],     W_m1[(size_t)k * HDw + t],       h0);
                h1 = fmaf(simg[k + 1], W_m1[(size_t)(k + 1) * HDw + t], h1);
                h2 = fmaf(simg[k + 2], W_m1[(size_t)(k + 2) * HDw + t], h2);
                h3 = fmaf(simg[k + 3], W_m1[(size_t)(k + 3) * HDw + t], h3);
            }
            contrib = fmaxf((h0 + h1) + (h2 + h3), 0.f) * W_m2[t];
        }
        red[t] = contrib;
        CBAR_LOCAL();
        for (int s = 128; s; s >>= 1) { if (t < s) red[t] += red[t + s]; CBAR_LOCAL(); }

        if (t == 0) {
            float li = red[0] + b_m2[0];
            float Z = fmaxf(0.5f * (sres[0] - fk), 0.f);
            float inner = sres[2] + sres[1] + sres[3] * expf(-sres[4] * Z);
            float lt = 1.f / (1.f + expf(-inner));
            oLam[d] = 1.f / (1.f + expf(-(lt + li)));
            oEta[d] = sres[3];
            oGamma[d] = sres[4];
            g_kci[d] = cnt;
        }
    }
    cbar();

    // ---- S9: Z_event patch region [0,160)^2 per doc (needs Z_ + kci) --------
    for (unsigned idx = (unsigned)ct; idx < 640000u; idx += (unsigned)TOTC) {
        unsigned d = idx / 6400u;
        unsigned rem = idx - d * 6400u;
        unsigned i = rem / 40u;
        unsigned q = rem - i * 40u;
        unsigned j0 = q << 2;
        int kd = g_kci[d];
        float4 v = {0.f, 0.f, 0.f, 0.f};
        if ((int)i < kd) {
            const float* zr = oZ + (size_t)i * NW + j0;
            float* vv = (float*)&v;
#pragma unroll
            for (int c = 0; c < 4; ++c) {
                int j = (int)j0 + c;
                if (j < kd && j != (int)i) {
                    float tt = 2.f - 2.f * zr[c];
                    vv[c] = expf(-tt * tt);
                }
            }
        }
        ((float4*)(oZev + (size_t)d * NW * NW + (size_t)i * NW))[q] = v;
    }
}

// ---------------------------------------------------------------------------
// Host launch: ONE kernel, ONE graph node.
// ---------------------------------------------------------------------------
extern "C" void kernel_launch(void* const* d_in, const int* in_sizes, int n_in,
                              void* d_out, int out_size) {
    (void)in_sizes; (void)n_in; (void)out_size;
    const void*  epoch  = d_in[0];
    const void*  epochs = d_in[1];
    const float* adj    = (const float*)d_in[2];
    const float* masks  = (const float*)d_in[3];
    const float* bows   = (const float*)d_in[4];
    const float* img    = (const float*)d_in[5];
    const float* W_g1   = (const float*)d_in[6];
    const float* W_g2   = (const float*)d_in[7];
    const float* W_h1   = (const float*)d_in[8];
    const float* b_h1   = (const float*)d_in[9];
    const float* W_h2   = (const float*)d_in[10];
    const float* b_h2   = (const float*)d_in[11];
    const float* W_mu2  = (const float*)d_in[12];
    const float* b_mu2  = (const float*)d_in[13];
    const float* W_eta2 = (const float*)d_in[14];
    const float* b_eta2 = (const float*)d_in[15];
    const float* W_gm2  = (const float*)d_in[16];
    const float* b_gm2  = (const float*)d_in[17];
    const float* w_m    = (const float*)d_in[18];
    const float* W_beta = (const float*)d_in[19];
    const float* W_m1   = (const float*)d_in[20];
    const float* b_m1   = (const float*)d_in[21];
    const float* W_m2   = (const float*)d_in[22];
    const float* b_m2   = (const float*)d_in[23];

    float* out = (float*)d_out;

    static bool attr_set = false;
    if (!attr_set) {
        cudaFuncSetAttribute(fused_ws, cudaFuncAttributeMaxDynamicSharedMemorySize,
                             FUSED_SMEM);
        attr_set = true;
    }

    fused_ws<<<NBLK, NT, FUSED_SMEM>>>(
        epoch, epochs, adj, masks, bows, img,
        W_g1, W_g2, W_h1, b_h1, W_h2, b_h2,
        W_mu2, b_mu2, W_eta2, b_eta2, W_gm2, b_gm2,
        w_m, W_beta, W_m1, b_m1, W_m2, b_m2,
        out + OFF_LAM, out + OFF_ZMAT, out + OFF_BETA,
        out + OFF_GAMMA, out + OFF_ETA, out + OFF_ZEV, out + OFF_H);
}

// round 12
// speedup vs baseline: 1.1387x; 1.1316x over previous
#include <cuda_runtime.h>
#include <cuda_bf16.h>
#include <math.h>
#include <stdint.h>

// ---------------------------------------------------------------------------
// Problem constants
// ---------------------------------------------------------------------------
#define NW 1000
#define ND 100
#define NF 100
#define TIw 512
#define HDw 128

// Output layout (concatenated f32)
#define OFF_LAM   0
#define OFF_ZMAT  100
#define OFF_BETA  1000100
#define OFF_GAMMA 1001100
#define OFF_ETA   1001200
#define OFF_ZEV   1001300
#define OFF_H     101001300

#define KMAX 160

// ---------------------------------------------------------------------------
// Device scratch
// ---------------------------------------------------------------------------
__device__ __align__(16) float g_T1[NW * NF];
__device__ __align__(16) float g_T2[NW * NF];
__device__ __align__(16) float g_heli[NW * NF];
__device__ float g_y[NW];
__device__ float g_wp[NF];
__device__ int   g_kci[ND];

#define CSR_CAP 96
__device__ int   g_ccnt[NW];
__device__ int   g_ccol[NW * CSR_CAP];
__device__ float g_cval[NW * CSR_CAP];

__device__ __forceinline__ float warp_sum(float v) {
#pragma unroll
    for (int o = 16; o; o >>= 1) v += __shfl_xor_sync(0xffffffffu, v, o);
    return v;
}

__device__ __forceinline__ float load_scalar(const void* p) {
    int v = *(const int*)p;
    if (v >= 0 && v <= 1000000) return (float)v;
    return *(const float*)p;
}

// ---------------------------------------------------------------------------
// Streams + events (static init; not during capture)
// ---------------------------------------------------------------------------
struct SideRes {
    cudaStream_t s_side, s_a, s_b;
    cudaEvent_t fork, ev_z, ev_t1, ev3, ev_beta, ev_final;
    SideRes() {
        int lo = 0, hi = 0;
        cudaDeviceGetStreamPriorityRange(&lo, &hi);
        cudaStreamCreateWithPriority(&s_side, cudaStreamNonBlocking, lo);
        cudaStreamCreateWithFlags(&s_a, cudaStreamNonBlocking);
        cudaStreamCreateWithFlags(&s_b, cudaStreamNonBlocking);
        cudaEventCreateWithFlags(&fork, cudaEventDisableTiming);
        cudaEventCreateWithFlags(&ev_z, cudaEventDisableTiming);
        cudaEventCreateWithFlags(&ev_t1, cudaEventDisableTiming);
        cudaEventCreateWithFlags(&ev3, cudaEventDisableTiming);
        cudaEventCreateWithFlags(&ev_beta, cudaEventDisableTiming);
        cudaEventCreateWithFlags(&ev_final, cudaEventDisableTiming);
    }
};
static SideRes g_sr;

// ---------------------------------------------------------------------------
// zev_zero (side stream) — round-10 proven shape: 67.8us @ 61.8% DRAM.
// ---------------------------------------------------------------------------
#define ZA4 (100u * 160u * 210u)
#define ZB4 (100u * 840u * 250u)
#define ZT4 (ZA4 + ZB4)

__global__ void __launch_bounds__(256)
zev_zero(float* __restrict__ zev) {
    float4 z = {0.f, 0.f, 0.f, 0.f};
    float4* p = (float4*)zev;
    unsigned g = blockIdx.x * blockDim.x + threadIdx.x;
    unsigned stride = gridDim.x * blockDim.x;
    for (; g < ZT4; g += stride) {
        unsigned off4;
        if (g < ZA4) {
            unsigned d = g / 33600u;
            unsigned rem = g - d * 33600u;
            unsigned i = rem / 210u;
            unsigned q = rem - i * 210u;
            off4 = d * 250000u + i * 250u + 40u + q;
        } else {
            unsigned h = g - ZA4;
            unsigned d = h / 210000u;
            unsigned rem = h - d * 210000u;
            unsigned i2 = rem / 250u;
            unsigned q = rem - i2 * 250u;
            off4 = d * 250000u + (160u + i2) * 250u + q;
        }
        p[off4] = z;
    }
}

// ---------------------------------------------------------------------------
// prep_k (r9 verbatim): adj CSR gather + prune mask
// ---------------------------------------------------------------------------
__global__ void prep_k(const float* __restrict__ adj,
                       const float* __restrict__ wm, const float* __restrict__ Wbeta,
                       const void* ep, const void* eps) {
    int t = threadIdx.x, lane = t & 31, wid = t >> 5;
    if (blockIdx.x < 250) {
        int row = blockIdx.x * 4 + wid;
        const float* r = adj + (size_t)row * NW;
        int cnt = 0;
        for (int base = 0; base < NW; base += 32) {
            int c = base + lane;
            float v = (c < NW) ? r[c] : 0.f;
            unsigned m = __ballot_sync(0xffffffffu, v != 0.f);
            while (m) {
                int b = __ffs(m) - 1;
                m &= m - 1;
                float vb = __shfl_sync(0xffffffffu, v, b);
                if (lane == 0 && cnt < CSR_CAP) {
                    g_ccol[row * CSR_CAP + cnt] = base + b;
                    g_cval[row * CSR_CAP + cnt] = vb;
                }
                ++cnt;
            }
        }
        if (lane == 0) g_ccnt[row] = min(cnt, CSR_CAP);
    } else if (t < NF) {
        float e1 = load_scalar(ep), e2 = load_scalar(eps);
        int j = (int)rintf((e1 / e2) * 0.3f * (float)NF);
        float wi = wm[t];
        int rank = 0;
        for (int l = 0; l < NF; ++l) {
            float wl = wm[l];
            if (wl < wi || (wl == wi && l < t)) ++rank;
        }
        g_wp[t] = (rank >= j) ? Wbeta[t] : 0.f;
    }
}

// ---------------------------------------------------------------------------
// gemm_k (r9 verbatim): used only for T1 = bows @ W_g1
// ---------------------------------------------------------------------------
__global__ void __launch_bounds__(128)
gemm_k(const float* __restrict__ A, const float* __restrict__ B,
       const float* __restrict__ bias, float* __restrict__ C, int flags) {
    __shared__ __align__(16) float sB[NF * NF];
    __shared__ __align__(16) float sA[8 * NF];
    __shared__ float sbias[NF];
    int t = threadIdx.x, lane = t & 31, w = t >> 5;
    int r0 = blockIdx.x * 8;

    for (int i = t; i < NF * NF / 4; i += 128)
        ((float4*)sB)[i] = ((const float4*)B)[i];
    for (int i = t; i < 8 * NF / 4; i += 128)
        ((float4*)sA)[i] = ((const float4*)(A + (size_t)r0 * NF))[i];
    if (t < NF) sbias[t] = bias ? bias[t] : 0.f;
    __syncthreads();

    float acc[2][4] = {};
#pragma unroll 4
    for (int k = 0; k < NF; ++k) {
        float b0 = sB[k * NF + lane];
        float b1 = sB[k * NF + lane + 32];
        float b2 = sB[k * NF + lane + 64];
        float b3 = (lane < 4) ? sB[k * NF + lane + 96] : 0.f;
#pragma unroll
        for (int rr = 0; rr < 2; ++rr) {
            float a = sA[(w * 2 + rr) * NF + k];
            acc[rr][0] = fmaf(a, b0, acc[rr][0]);
            acc[rr][1] = fmaf(a, b1, acc[rr][1]);
            acc[rr][2] = fmaf(a, b2, acc[rr][2]);
            acc[rr][3] = fmaf(a, b3, acc[rr][3]);
        }
    }
    float bb0 = sbias[lane], bb1 = sbias[lane + 32], bb2 = sbias[lane + 64];
    float bb3 = (lane < 4) ? sbias[lane + 96] : 0.f;
#pragma unroll
    for (int rr = 0; rr < 2; ++rr) {
        acc[rr][0] += bb0; acc[rr][1] += bb1; acc[rr][2] += bb2; acc[rr][3] += bb3;
        if (flags & 1) {
            acc[rr][0] = fmaxf(acc[rr][0], 0.f);
            acc[rr][1] = fmaxf(acc[rr][1], 0.f);
            acc[rr][2] = fmaxf(acc[rr][2], 0.f);
            acc[rr][3] = fmaxf(acc[rr][3], 0.f);
        }
        float* Cr = C + (size_t)(r0 + w * 2 + rr) * NF;
        Cr[lane] = acc[rr][0];
        Cr[lane + 32] = acc[rr][1];
        Cr[lane + 64] = acc[rr][2];
        if (lane < 4) Cr[lane + 96] = acc[rr][3];
    }
}

// ---------------------------------------------------------------------------
// rowfuse1: block per row r — H1[r]=relu(spmm(T1)) then T2[r]=H1[r]@W_g2.
// W_g2 read coalesced from global (L1-cached across blocks).
// ---------------------------------------------------------------------------
__global__ void __launch_bounds__(128)
rowfuse1(const float* __restrict__ T1, const float* __restrict__ Wg2,
         float* __restrict__ T2) {
    __shared__ int   scol[CSR_CAP];
    __shared__ float sval[CSR_CAP];
    __shared__ float sH1[NF];
    int r = blockIdx.x, t = threadIdx.x;
    int nnz = g_ccnt[r];
    if (t < nnz) {
        scol[t] = g_ccol[r * CSR_CAP + t];
        sval[t] = g_cval[r * CSR_CAP + t];
    }
    __syncthreads();
    if (t < NF) {
        float h = 0.f;
#pragma unroll 4
        for (int q = 0; q < nnz; ++q)
            h = fmaf(sval[q], T1[(size_t)scol[q] * NF + t], h);
        sH1[t] = fmaxf(h, 0.f);
    }
    __syncthreads();
    if (t < NF) {
        float acc = 0.f;
#pragma unroll 4
        for (int k = 0; k < NF; ++k)
            acc = fmaf(sH1[k], Wg2[(size_t)k * NF + t], acc);
        T2[(size_t)r * NF + t] = acc;
    }
}

// ---------------------------------------------------------------------------
// rowfuse2: block per row r — H[r]=spmm(T2) -> oH ; y[r]=H[r].wp ;
// E1[r]=relu(H W_h1+b) ; heli[r]=l2norm(relu(E1 W_h2+b)).
// ---------------------------------------------------------------------------
__global__ void __launch_bounds__(128)
rowfuse2(const float* __restrict__ T2,
         const float* __restrict__ Wh1, const float* __restrict__ bh1,
         const float* __restrict__ Wh2, const float* __restrict__ bh2,
         float* __restrict__ oH, float* __restrict__ heli) {
    __shared__ int   scol[CSR_CAP];
    __shared__ float sval[CSR_CAP];
    __shared__ float sH[NF];
    __shared__ float sE[NF];
    __shared__ float red[128];
    int r = blockIdx.x, t = threadIdx.x;
    int nnz = g_ccnt[r];
    if (t < nnz) {
        scol[t] = g_ccol[r * CSR_CAP + t];
        sval[t] = g_cval[r * CSR_CAP + t];
    }
    __syncthreads();
    if (t < NF) {
        float h = 0.f;
#pragma unroll 4
        for (int q = 0; q < nnz; ++q)
            h = fmaf(sval[q], T2[(size_t)scol[q] * NF + t], h);
        sH[t] = h;
        oH[(size_t)r * NF + t] = h;
    }
    __syncthreads();
    // y[r] = dot(H[r], wp)
    red[t] = (t < NF) ? sH[t] * g_wp[t] : 0.f;
    __syncthreads();
    for (int s = 64; s; s >>= 1) { if (t < s) red[t] += red[t + s]; __syncthreads(); }
    if (t == 0) g_y[r] = red[0];
    // E1
    if (t < NF) {
        float e = bh1[t];
#pragma unroll 4
        for (int k = 0; k < NF; ++k)
            e = fmaf(sH[k], Wh1[(size_t)k * NF + t], e);
        sE[t] = fmaxf(e, 0.f);
    }
    __syncthreads();
    // heli (pre-norm), sum of squares
    float hh = 0.f;
    if (t < NF) {
        hh = bh2[t];
#pragma unroll 4
        for (int k = 0; k < NF; ++k)
            hh = fmaf(sE[k], Wh2[(size_t)k * NF + t], hh);
        hh = fmaxf(hh, 0.f);
    }
    red[t] = (t < NF) ? hh * hh : 0.f;
    __syncthreads();
    for (int s = 64; s; s >>= 1) { if (t < s) red[t] += red[t + s]; __syncthreads(); }
    float inv = 1.f / fmaxf(sqrtf(red[0]), 1e-12f);
    if (t < NF) heli[(size_t)r * NF + t] = hh * inv;
}

// ---------------------------------------------------------------------------
// beta_norm (r9 verbatim)
// ---------------------------------------------------------------------------
__global__ void __launch_bounds__(1024)
beta_norm(float* __restrict__ oBeta) {
    __shared__ float red[1024];
    int t = threadIdx.x;
    float y = (t < NW) ? g_y[t] : 0.f;
    red[t] = y * y;
    __syncthreads();
    for (int s = 512; s; s >>= 1) {
        if (t < s) red[t] += red[t + s];
        __syncthreads();
    }
    float inv = 1.f / fmaxf(sqrtf(red[0]), 1e-12f);
    if (t < NW) oBeta[t] = y * inv;
}

// ---------------------------------------------------------------------------
// gemm_nt_relu (round-2 VERBATIM — protected, passed 4x)
// ---------------------------------------------------------------------------
__global__ void gemm_nt_relu(const float* __restrict__ A, float* __restrict__ C,
                             int M, int K) {
    __shared__ float sA[64][21];
    __shared__ float sB[64][21];
    int tx = threadIdx.x, ty = threadIdx.y;
    int tid = ty * 16 + tx;
    int ib = blockIdx.y * 64, jb = blockIdx.x * 64;
    float acc[4][4] = {};
    for (int k0 = 0; k0 < K; k0 += 20) {
        for (int l = tid; l < 64 * 20; l += 256) {
            int r = l / 20, c = l - r * 20;
            int kk = k0 + c;
            sA[r][c] = (ib + r < M && kk < K) ? A[(size_t)(ib + r) * K + kk] : 0.f;
            sB[r][c] = (jb + r < M && kk < K) ? A[(size_t)(jb + r) * K + kk] : 0.f;
        }
        __syncthreads();
#pragma unroll
        for (int kk = 0; kk < 20; ++kk) {
            float a[4], b[4];
#pragma unroll
            for (int r = 0; r < 4; ++r) a[r] = sA[ty * 4 + r][kk];
#pragma unroll
            for (int c = 0; c < 4; ++c) b[c] = sB[tx * 4 + c][kk];
#pragma unroll
            for (int r = 0; r < 4; ++r)
#pragma unroll
                for (int c = 0; c < 4; ++c) acc[r][c] = fmaf(a[r], b[c], acc[r][c]);
        }
        __syncthreads();
    }
#pragma unroll
    for (int r = 0; r < 4; ++r) {
        int i = ib + ty * 4 + r;
        if (i >= M) continue;
#pragma unroll
        for (int c = 0; c < 4; ++c) {
            int j = jb + tx * 4 + c;
            if (j >= M) continue;
            C[(size_t)i * M + j] = fmaxf(acc[r][c], 0.f);
        }
    }
}

// ---------------------------------------------------------------------------
// doc_k (r9 verbatim)
// ---------------------------------------------------------------------------
__global__ void __launch_bounds__(512)
doc_k(const float* __restrict__ masks, const float* __restrict__ H,
      const float* __restrict__ heli, const float* __restrict__ beta_,
      const float* __restrict__ W_mu2, const float* __restrict__ b_mu2,
      const float* __restrict__ W_eta2, const float* __restrict__ b_eta2,
      const float* __restrict__ W_gm2, const float* __restrict__ b_gm2,
      const float* __restrict__ img, const float* __restrict__ W_m1,
      const float* __restrict__ b_m1, const float* __restrict__ W_m2,
      const float* __restrict__ b_m2,
      float* __restrict__ oLam, float* __restrict__ oEta,
      float* __restrict__ oGamma) {
    __shared__ int   cols[KMAX];
    __shared__ float red[512];
    __shared__ float hp[128];
    __shared__ float simg[TIw];
    __shared__ float sres[8];
    __shared__ int s_cnt;

    int d = blockIdx.x, t = threadIdx.x, lane = t & 31, wid = t >> 5;

    if (wid == 0) {
        const float* mrow = masks + (size_t)d * NW;
        int cnt = 0;
        for (int base = 0; base < NW; base += 32) {
            int c = base + lane;
            float v = (c < NW) ? mrow[c] : 0.f;
            unsigned m = __ballot_sync(0xffffffffu, v != 0.f);
            while (m) {
                int b = __ffs(m) - 1;
                m &= m - 1;
                if (lane == 0 && cnt < KMAX) cols[cnt] = base + b;
                ++cnt;
            }
        }
        if (lane == 0) s_cnt = min(cnt, KMAX);
    }
    __syncthreads();
    int cnt = s_cnt;
    float fk = (float)cnt;

    float sv = 0.f;
    if (t < NF) {
        float hpv = 0.f;
#pragma unroll 4
        for (int q = 0; q < cnt; ++q) {
            int c = cols[q];
            hpv += H[(size_t)c * NF + t];
            sv += heli[(size_t)c * NF + t];
        }
        hp[t] = hpv / fmaxf(fk, 1.f);
    }
    red[t] = (t < NF) ? sv * sv : 0.f;
    __syncthreads();
    for (int s = 256; s; s >>= 1) { if (t < s) red[t] += red[t + s]; __syncthreads(); }
    if (t == 0) sres[0] = red[0];
    __syncthreads();

    red[t] = (t < cnt) ? beta_[cols[t]] : 0.f;
    __syncthreads();
    for (int s = 256; s; s >>= 1) { if (t < s) red[t] += red[t + s]; __syncthreads(); }
    if (t == 0) sres[1] = red[0];
    __syncthreads();

    float hpt = (t < NF) ? hp[t] : 0.f;
    red[t] = (t < NF) ? hpt * W_mu2[t] : 0.f;
    __syncthreads();
    for (int s = 256; s; s >>= 1) { if (t < s) red[t] += red[t + s]; __syncthreads(); }
    if (t == 0) sres[2] = fmaxf(red[0] + b_mu2[0], 0.f);
    __syncthreads();
    red[t] = (t < NF) ? hpt * W_eta2[t] : 0.f;
    __syncthreads();
    for (int s = 256; s; s >>= 1) { if (t < s) red[t] += red[t + s]; __syncthreads(); }
    if (t == 0) sres[3] = fmaxf(red[0] + b_eta2[0], 0.f);
    __syncthreads();
    red[t] = (t < NF) ? hpt * W_gm2[t] : 0.f;
    __syncthreads();
    for (int s = 256; s; s >>= 1) { if (t < s) red[t] += red[t + s]; __syncthreads(); }
    if (t == 0) sres[4] = fmaxf(red[0] + b_gm2[0], 0.f);
    __syncthreads();

    for (int k = t; k < TIw; k += 512) simg[k] = img[(size_t)d * TIw + k];
    __syncthreads();
    float contrib = 0.f;
    if (t < HDw) {
        float h0 = b_m1[t], h1 = 0.f, h2 = 0.f, h3 = 0.f;
#pragma unroll 4
        for (int k = 0; k < TIw; k += 4) {
            h0 = fmaf(simg[k],     W_m1[(size_t)k * HDw + t],       h0);
            h1 = fmaf(simg[k + 1], W_m1[(size_t)(k + 1) * HDw + t], h1);
            h2 = fmaf(simg[k + 2], W_m1[(size_t)(k + 2) * HDw + t], h2);
            h3 = fmaf(simg[k + 3], W_m1[(size_t)(k + 3) * HDw + t], h3);
        }
        contrib = fmaxf((h0 + h1) + (h2 + h3), 0.f) * W_m2[t];
    }
    red[t] = contrib;
    __syncthreads();
    for (int s = 256; s; s >>= 1) { if (t < s) red[t] += red[t + s]; __syncthreads(); }

    if (t == 0) {
        float li = red[0] + b_m2[0];
        float Z = fmaxf(0.5f * (sres[0] - fk), 0.f);
        float inner = sres[2] + sres[1] + sres[3] * expf(-sres[4] * Z);
        float lt = 1.f / (1.f + expf(-inner));
        oLam[d] = 1.f / (1.f + expf(-(lt + li)));
        oEta[d] = sres[3];
        oGamma[d] = sres[4];
        g_kci[d] = cnt;
    }
}

// ---------------------------------------------------------------------------
// zev_patch (r9 verbatim)
// ---------------------------------------------------------------------------
__global__ void __launch_bounds__(256)
zev_patch(const float* __restrict__ oZ, float* __restrict__ zev) {
    unsigned g = blockIdx.x * 256u + threadIdx.x;
    if (g >= 640000u) return;
    unsigned d = g / 6400u;
    unsigned rem = g - d * 6400u;
    unsigned i = rem / 40u;
    unsigned q = rem - i * 40u;
    unsigned j0 = q << 2;
    int kd = g_kci[d];
    float4 v = {0.f, 0.f, 0.f, 0.f};
    if ((int)i < kd) {
        const float* zr = oZ + (size_t)i * NW + j0;
        float* vv = (float*)&v;
#pragma unroll
        for (int c = 0; c < 4; ++c) {
            int j = (int)j0 + c;
            if (j < kd && j != (int)i) {
                float tt = 2.f - 2.f * zr[c];
                vv[c] = expf(-tt * tt);
            }
        }
    }
    *(float4*)(zev + (size_t)d * NW * NW + (size_t)i * NW + j0) = v;
}

// ---------------------------------------------------------------------------
// Host launch — depth-6 DAG on explicit streams
// ---------------------------------------------------------------------------
extern "C" void kernel_launch(void* const* d_in, const int* in_sizes, int n_in,
                              void* d_out, int out_size) {
    (void)in_sizes; (void)n_in; (void)out_size;
    const void*  epoch  = d_in[0];
    const void*  epochs = d_in[1];
    const float* adj    = (const float*)d_in[2];
    const float* masks  = (const float*)d_in[3];
    const float* bows   = (const float*)d_in[4];
    const float* img    = (const float*)d_in[5];
    const float* W_g1   = (const float*)d_in[6];
    const float* W_g2   = (const float*)d_in[7];
    const float* W_h1   = (const float*)d_in[8];
    const float* b_h1   = (const float*)d_in[9];
    const float* W_h2   = (const float*)d_in[10];
    const float* b_h2   = (const float*)d_in[11];
    const float* W_mu2  = (const float*)d_in[12];
    const float* b_mu2  = (const float*)d_in[13];
    const float* W_eta2 = (const float*)d_in[14];
    const float* b_eta2 = (const float*)d_in[15];
    const float* W_gm2  = (const float*)d_in[16];
    const float* b_gm2  = (const float*)d_in[17];
    const float* w_m    = (const float*)d_in[18];
    const float* W_beta = (const float*)d_in[19];
    const float* W_m1   = (const float*)d_in[20];
    const float* b_m1   = (const float*)d_in[21];
    const float* W_m2   = (const float*)d_in[22];
    const float* b_m2   = (const float*)d_in[23];

    float* out = (float*)d_out;
    float* oLam   = out + OFF_LAM;
    float* oZ     = out + OFF_ZMAT;
    float* oBeta  = out + OFF_BETA;
    float* oGamma = out + OFF_GAMMA;
    float* oEta   = out + OFF_ETA;
    float* oZev   = out + OFF_ZEV;
    float* oH     = out + OFF_H;

    float *pT1, *pT2, *pHeli;
    cudaGetSymbolAddress((void**)&pT1, g_T1);
    cudaGetSymbolAddress((void**)&pT2, g_T2);
    cudaGetSymbolAddress((void**)&pHeli, g_heli);

    // fork from capture stream
    cudaEventRecord(g_sr.fork, 0);

    // side: Z_event zero region (independent)
    cudaStreamWaitEvent(g_sr.s_side, g_sr.fork, 0);
    zev_zero<<<296, 256, 0, g_sr.s_side>>>(oZev);
    cudaEventRecord(g_sr.ev_z, g_sr.s_side);

    // s_b: T1 = bows @ W_g1 (depth 1, parallel with prep)
    cudaStreamWaitEvent(g_sr.s_b, g_sr.fork, 0);
    gemm_k<<<125, 128, 0, g_sr.s_b>>>(bows, W_g1, nullptr, pT1, 0);
    cudaEventRecord(g_sr.ev_t1, g_sr.s_b);

    // s_a: prep (depth 1)
    cudaStreamWaitEvent(g_sr.s_a, g_sr.fork, 0);
    prep_k<<<251, 128, 0, g_sr.s_a>>>(adj, w_m, W_beta, epoch, epochs);

    // depth 2: rowfuse1 (H1 -> T2), needs CSR (in-stream) + T1 (event)
    cudaStreamWaitEvent(g_sr.s_a, g_sr.ev_t1, 0);
    rowfuse1<<<NW, 128, 0, g_sr.s_a>>>(pT1, W_g2, pT2);

    // depth 3: rowfuse2 (H, y, E1, heli)
    rowfuse2<<<NW, 128, 0, g_sr.s_a>>>(pT2, W_h1, b_h1, W_h2, b_h2, oH, pHeli);
    cudaEventRecord(g_sr.ev3, g_sr.s_a);

    // depth 4 (parallel): beta_norm on s_b ; zgemm on s_a
    cudaStreamWaitEvent(g_sr.s_b, g_sr.ev3, 0);
    beta_norm<<<1, 1024, 0, g_sr.s_b>>>(oBeta);
    cudaEventRecord(g_sr.ev_beta, g_sr.s_b);

    {
        dim3 grid((NW + 63) / 64, (NW + 63) / 64);
        dim3 block(16, 16);
        gemm_nt_relu<<<grid, block, 0, g_sr.s_a>>>(pHeli, oZ, NW, NF);
    }

    // depth 5: doc (needs beta + heli + H)
    cudaStreamWaitEvent(g_sr.s_a, g_sr.ev_beta, 0);
    doc_k<<<ND, 512, 0, g_sr.s_a>>>(masks, oH, pHeli, oBeta,
                                    W_mu2, b_mu2, W_eta2, b_eta2, W_gm2, b_gm2,
                                    img, W_m1, b_m1, W_m2, b_m2,
                                    oLam, oEta, oGamma);

    // depth 6: patch (needs Z_, kci, zero region)
    cudaStreamWaitEvent(g_sr.s_a, g_sr.ev_z, 0);
    zev_patch<<<2500, 256, 0, g_sr.s_a>>>(oZ, oZev);
    cudaEventRecord(g_sr.ev_final, g_sr.s_a);

    // join back to the capture stream
    cudaStreamWaitEvent(0, g_sr.ev_final, 0);
}